// round 14
// baseline (speedup 1.0000x reference)
#include <cuda_runtime.h>
#include <cstdint>
#include <cstdio>

#define NB   2
#define NN   50000
#define HH   64
#define NE   1000000
#define NOBS 128
#define NA   18
#define NAFF 512
#define NEFF 256
#define PB   196

#define NBLK   148
#define NW     24
#define NTHR   768
#define WTOT   (NBLK * NW)     // 3552 warps
#define GROUP  4
#define WIN    384             // idx window (ints) per warp

// chunk split: NN = WTOT*14 + 272  ->  first 272 warps take 15 nodes
#define CHUNK_BIG   15
#define CHUNK_SMALL 14
#define NBIG        (NN - WTOT * CHUNK_SMALL)   // 272

typedef unsigned int u32;
typedef unsigned long long ull;

// ---------------- device scratch ----------------
__device__ float g_Wp[128 * 128];             // fused weight [k][c]
__device__ float g_projG[NB * HH];
__device__ float g_projC[NB * HH];
__device__ int   g_flag[NN];
__device__ int   g_cnt[NN];
__device__ int   g_off[NN + 1];
__device__ int   g_cur[NN];
__device__ int   g_esrc[NE + WIN];            // padded for cp.async overread
__device__ int   g_part[256];
__device__ unsigned g_sbar;                   // scan grid barrier
__device__ unsigned g_fbar;                   // fused grid barrier

// ---------------- helpers ----------------
__device__ __forceinline__ void fma2(ull& d, ull a, ull b) {
    asm("fma.rn.f32x2 %0, %1, %2, %0;" : "+l"(d) : "l"(a), "l"(b));
}
__device__ __forceinline__ void add2(ull& d, ull a) {
    asm("add.rn.f32x2 %0, %0, %1;" : "+l"(d) : "l"(a));
}
__device__ __forceinline__ ull splat2(float w) {
    ull r; unsigned u = __float_as_uint(w);
    asm("mov.b64 %0, {%1, %1};" : "=l"(r) : "r"(u));
    return r;
}
__device__ __forceinline__ ull pack2(float a, float b) {
    ull r;
    asm("mov.b64 %0, {%1, %2};" : "=l"(r) : "r"(__float_as_uint(a)), "r"(__float_as_uint(b)));
    return r;
}
__device__ __forceinline__ float2 u2f2(ull v) {
    float2 f;
    f.x = __uint_as_float((unsigned)v);
    f.y = __uint_as_float((unsigned)(v >> 32));
    return f;
}
__device__ __forceinline__ void cpa16(void* dst, const void* src) {
    unsigned d = (unsigned)__cvta_generic_to_shared(dst);
    asm volatile("cp.async.cg.shared.global [%0], [%1], 16;" :: "r"(d), "l"(src));
}
__device__ __forceinline__ int warp_incl_scan(int v) {
    int lane = threadIdx.x & 31;
#pragma unroll
    for (int d = 1; d < 32; d <<= 1) {
        int t = __shfl_up_sync(0xffffffffu, v, d);
        if (lane >= d) v += t;
    }
    return v;
}
__device__ __forceinline__ float sigm(float x) { return __fdividef(1.f, 1.f + __expf(-x)); }
__device__ __forceinline__ float tanha(float x) { return 1.f - __fdividef(2.f, __expf(2.f * x) + 1.f); }

// grid barrier: all blocks arrive, thread 0 spins on volatile load
__device__ __forceinline__ void grid_barrier(unsigned* bar, unsigned expected) {
    __syncthreads();
    if (threadIdx.x == 0) {
        __threadfence();
        atomicAdd(bar, 1u);
        volatile unsigned* vb = bar;
        while (*vb < expected) { }
    }
    __syncthreads();
}

// ---------------- K1: merged prep (proj + flags + fused weight + zeroing) ----------------
__global__ void prep_kernel(const float* __restrict__ obs,
                            const float* __restrict__ W_in,
                            const float* __restrict__ b_in,
                            const float* __restrict__ W_msg,
                            const float* __restrict__ W_gate,
                            const float* __restrict__ W_cand,
                            const int* __restrict__ afferent_idx) {
    if (blockIdx.x == 128) {
        int t = threadIdx.x;
        if (t == 0) { g_sbar = 0u; g_fbar = 0u; }
        int4 z4 = make_int4(0, 0, 0, 0);
        for (int i = t; i < NN / 4; i += 128)
            ((int4*)g_flag)[i] = z4;
        __syncthreads();
        __shared__ float proj[NB * HH];
        int b = t >> 6, h = t & 63;
        float acc = b_in[h];
        for (int o = 0; o < NOBS; o++)
            acc += obs[b * NOBS + o] * W_in[o * HH + h];
        proj[b * HH + h] = acc;
        __syncthreads();
        float ag = 0.f, ac = 0.f;
        for (int k = 0; k < HH; k++) {
            float p = proj[b * HH + k];
            ag += p * W_gate[(HH + k) * HH + h];
            ac += p * W_cand[(HH + k) * HH + h];
        }
        g_projG[b * HH + h] = ag;
        g_projC[b * HH + h] = ac;
        for (int i = t; i < NAFF; i += 128)
            g_flag[afferent_idx[i]] = 1;
    } else {
        const int per = (NN + 127) / 128;   // 391
        int s = blockIdx.x * per;
        int e = s + per; if (e > NN) e = NN;
        for (int i = s + threadIdx.x; i < e; i += 128)
            g_cnt[i] = 0;
        int c = blockIdx.x;     // output column 0..127
        int k = threadIdx.x;    // input row 0..127
        float w;
        if (k < HH) {
            w = (c < HH) ? W_gate[k * HH + c] : W_cand[k * HH + (c - HH)];
        } else {
            int km = k - HH;
            float acc = 0.f;
            if (c < HH) {
                for (int t2 = 0; t2 < HH; t2++)
                    acc += W_msg[km * HH + t2] * W_gate[(HH + t2) * HH + c];
            } else {
                for (int t2 = 0; t2 < HH; t2++)
                    acc += W_msg[km * HH + t2] * W_cand[(HH + t2) * HH + (c - HH)];
            }
            w = acc;
        }
        g_Wp[k * 128 + c] = w;
    }
}

// ---------------- K2: histogram ----------------
__global__ void hist_kernel(const int4* __restrict__ dst4) {
    int i = (blockIdx.x * blockDim.x + threadIdx.x) * 2;
    if (i < NE / 4) {
        int4 d0 = __ldg(dst4 + i);
        int4 d1 = __ldg(dst4 + i + 1);
        atomicAdd(&g_cnt[d0.x], 1);
        atomicAdd(&g_cnt[d0.y], 1);
        atomicAdd(&g_cnt[d0.z], 1);
        atomicAdd(&g_cnt[d0.w], 1);
        atomicAdd(&g_cnt[d1.x], 1);
        atomicAdd(&g_cnt[d1.y], 1);
        atomicAdd(&g_cnt[d1.z], 1);
        atomicAdd(&g_cnt[d1.w], 1);
    }
}

// ---------------- K3: single-launch scan ----------------
__global__ void scan_kernel() {            // grid PB, 256 thr
    int b = blockIdx.x;
    int i = b * 256 + threadIdx.x;
    int t = threadIdx.x;
    int lane = t & 31, w = t >> 5;
    __shared__ int ws[8];
    __shared__ int blockBase;

    int v = (i < NN) ? g_cnt[i] : 0;

    int s = v;
#pragma unroll
    for (int d = 16; d > 0; d >>= 1) s += __shfl_down_sync(0xffffffffu, s, d);
    if (lane == 0) ws[w] = s;
    __syncthreads();
    if (t == 0) {
        int tot = 0;
        for (int x = 0; x < 8; x++) tot += ws[x];
        g_part[b] = tot;
    }
    grid_barrier(&g_sbar, PB);

    int pv = (t < PB && t < b) ? g_part[t] : 0;
#pragma unroll
    for (int d = 16; d > 0; d >>= 1) pv += __shfl_down_sync(0xffffffffu, pv, d);
    if (lane == 0) ws[w] = pv;
    __syncthreads();
    if (t == 0) {
        int bs = 0;
        for (int x = 0; x < 8; x++) bs += ws[x];
        blockBase = bs;
    }
    __syncthreads();

    int inc = warp_incl_scan(v);
    if (lane == 31) ws[w] = inc;
    __syncthreads();
    if (w == 0) {
        int qv = (lane < 8) ? ws[lane] : 0;
        int qi = warp_incl_scan(qv);
        if (lane < 8) ws[lane] = qi;
    }
    __syncthreads();
    int base = (w > 0) ? ws[w - 1] : 0;
    int off = blockBase + base + inc - v;
    if (i < NN) { g_off[i] = off; g_cur[i] = off; }
    if (i == 0) g_off[NN] = NE;
}

// ---------------- K4: fused scatter + gather + f32x2 GEMM + GRU epilogue ----------------
// 24 warps/block, 1 block/SM (occupancy fix: issue was 41.6% at 16 warps).
__global__ void __launch_bounds__(NTHR, 1) fused_kernel(const int4* __restrict__ src4,
                                                        const int4* __restrict__ dst4,
                                                        const float* __restrict__ state,
                                                        const float* __restrict__ b_gate,
                                                        const float* __restrict__ b_cand,
                                                        float* __restrict__ out_ns) {
    extern __shared__ float smem[];
    float* Ws = smem;                                    // 16384 floats
    ull* xs = (ull*)(smem + 16384);                      // NW * GROUP * 128 ull
    int* sIdx = (int*)(xs + NW * GROUP * 128);           // NW * WIN ints

    int tid = threadIdx.x;

    // ---- phase A: CSR scatter (striped over all threads) ----
    {
        int gtid = blockIdx.x * NTHR + tid;
        for (int i = gtid; i < NE / 4; i += NBLK * NTHR) {
            int4 s0 = __ldg(src4 + i);
            int4 d0 = __ldg(dst4 + i);
            g_esrc[atomicAdd(&g_cur[d0.x], 1)] = s0.x;
            g_esrc[atomicAdd(&g_cur[d0.y], 1)] = s0.y;
            g_esrc[atomicAdd(&g_cur[d0.z], 1)] = s0.z;
            g_esrc[atomicAdd(&g_cur[d0.w], 1)] = s0.w;
        }
    }

    // load W while scatter drains, then grid barrier
    for (int i = tid; i < 4096; i += NTHR)
        ((float4*)Ws)[i] = ((const float4*)g_Wp)[i];
    grid_barrier(&g_fbar, NBLK);

    int warp = tid >> 5, lane = tid & 31;
    int q = lane & 15;
    int cc0 = q * 4;
    bool zside = lane < 16;
    int l4 = lane & 15;
    int half = lane >> 4;      // 0: batch0, 1: batch1

    float bias[4], pj0[4], pj1[4];
#pragma unroll
    for (int c = 0; c < 4; c++) {
        int cc = cc0 + c;
        if (zside) { bias[c] = __ldg(b_gate + cc); pj0[c] = g_projG[cc]; pj1[c] = g_projG[64 + cc]; }
        else       { bias[c] = __ldg(b_cand + cc); pj0[c] = g_projC[cc]; pj1[c] = g_projC[64 + cc]; }
    }

    ull* mx = xs + warp * (GROUP * 128);
    int* widx = sIdx + warp * WIN;
    int gwid = blockIdx.x * NW + warp;
    const ulonglong2* U2 = (const ulonglong2*)state + (size_t)half * NN * 16;

    int cBase, cCnt;
    if (gwid < NBIG) { cBase = gwid * CHUNK_BIG; cCnt = CHUNK_BIG; }
    else             { cBase = NBIG * CHUNK_BIG + (gwid - NBIG) * CHUNK_SMALL; cCnt = CHUNK_SMALL; }
    int nEnd = cBase + cCnt;

    // stage index window for the chunk
    int slab = __ldg(&g_off[cBase]) & ~3;
    for (int c = lane; c < WIN / 4; c += 32)
        cpa16(widx + c * 4, g_esrc + slab + c * 4);
    asm volatile("cp.async.commit_group;" ::: "memory");
    asm volatile("cp.async.wait_group 0;" ::: "memory");
    __syncwarp();

    int sg = 1 + (gwid % GROUP);       // staggered first sub-group size
    int n0 = cBase;
    while (n0 < nEnd) {
        int cnt = nEnd - n0;
        if (cnt > sg) cnt = sg;
        sg = GROUP;
        int flg[GROUP];

        // ---- gather phase (split-batch LDG.128 + f32x2 accumulate, 4-unroll) ----
        for (int m = 0; m < cnt; m++) {
            int n = n0 + m;
            int beg = __ldg(&g_off[n]), end = __ldg(&g_off[n + 1]);
            flg[m] = __ldg(&g_flag[n]);
            ull a0 = 0ull, a1 = 0ull;
            int j = beg;
            while (j < end) {
                if (j >= slab + WIN) {           // refill window
                    slab = j & ~3;
                    for (int c = lane; c < WIN / 4; c += 32)
                        cpa16(widx + c * 4, g_esrc + slab + c * 4);
                    asm volatile("cp.async.commit_group;" ::: "memory");
                    asm volatile("cp.async.wait_group 0;" ::: "memory");
                    __syncwarp();
                }
                int lim = slab + WIN;
                if (lim > end) lim = end;
                for (; j + 4 <= lim; j += 4) {
                    int e0 = widx[j - slab],     e1 = widx[j - slab + 1];
                    int e2 = widx[j - slab + 2], e3 = widx[j - slab + 3];
                    ulonglong2 v0 = __ldg(U2 + (size_t)e0 * 16 + l4);
                    ulonglong2 v1 = __ldg(U2 + (size_t)e1 * 16 + l4);
                    ulonglong2 v2 = __ldg(U2 + (size_t)e2 * 16 + l4);
                    ulonglong2 v3 = __ldg(U2 + (size_t)e3 * 16 + l4);
                    add2(a0, v0.x); add2(a1, v0.y);
                    add2(a0, v1.x); add2(a1, v1.y);
                    add2(a0, v2.x); add2(a1, v2.y);
                    add2(a0, v3.x); add2(a1, v3.y);
                }
                for (; j < lim; j++) {
                    int e0 = widx[j - slab];
                    ulonglong2 v0 = __ldg(U2 + (size_t)e0 * 16 + l4);
                    add2(a0, v0.x);
                    add2(a1, v0.y);
                }
            }
            ulonglong2 so = __ldg(U2 + (size_t)n * 16 + l4);
            ull po0 = __shfl_xor_sync(0xffffffffu, so.x, 16);
            ull po1 = __shfl_xor_sync(0xffffffffu, so.y, 16);
            ull qa0 = __shfl_xor_sync(0xffffffffu, a0, 16);
            ull qa1 = __shfl_xor_sync(0xffffffffu, a1, 16);
            ull* row = mx + m * 128;
            if (lane < 16) {
                float2 o0 = u2f2(so.x), o1 = u2f2(so.y);   // b0 state
                float2 p0 = u2f2(po0),  p1 = u2f2(po1);    // b1 state
                ((float4*)row)[2 * l4]     = make_float4(o0.x, p0.x, o0.y, p0.y);
                ((float4*)row)[2 * l4 + 1] = make_float4(o1.x, p1.x, o1.y, p1.y);
            } else {
                float2 o0 = u2f2(a0),  o1 = u2f2(a1);      // b1 agg
                float2 p0 = u2f2(qa0), p1 = u2f2(qa1);     // b0 agg
                ((float4*)(row + 64))[2 * l4]     = make_float4(p0.x, o0.x, p0.y, o0.y);
                ((float4*)(row + 64))[2 * l4 + 1] = make_float4(p1.x, o1.x, p1.y, o1.y);
            }
        }
        __syncwarp();

        // ---- FMA phase (batch-paired, splat weights) ----
        ull acc6[GROUP][4];
#pragma unroll
        for (int m = 0; m < GROUP; m++)
#pragma unroll
            for (int c = 0; c < 4; c++) acc6[m][c] = 0ull;

#pragma unroll 4
        for (int k = 0; k < 128; k += 2) {
            float4 wA = ((const float4*)(Ws + k * 128))[lane];
            float4 wB = ((const float4*)(Ws + (k + 1) * 128))[lane];
            ull wa0 = splat2(wA.x), wa1 = splat2(wA.y), wa2 = splat2(wA.z), wa3 = splat2(wA.w);
            ull wb0 = splat2(wB.x), wb1 = splat2(wB.y), wb2 = splat2(wB.z), wb3 = splat2(wB.w);
#pragma unroll
            for (int m = 0; m < GROUP; m++) {
                ulonglong2 xv = ((const ulonglong2*)(mx + m * 128))[k >> 1];
                fma2(acc6[m][0], wa0, xv.x); fma2(acc6[m][1], wa1, xv.x);
                fma2(acc6[m][2], wa2, xv.x); fma2(acc6[m][3], wa3, xv.x);
                fma2(acc6[m][0], wb0, xv.y); fma2(acc6[m][1], wb1, xv.y);
                fma2(acc6[m][2], wb2, xv.y); fma2(acc6[m][3], wb3, xv.y);
            }
        }

        // ---- epilogue ----
        for (int m = 0; m < cnt; m++) {
            int n = n0 + m;
            ull actp[4];
#pragma unroll
            for (int c = 0; c < 4; c++) {
                float2 pre = u2f2(acc6[m][c]);
                float p0 = pre.x + bias[c] + (flg[m] ? pj0[c] : 0.f);
                float p1 = pre.y + bias[c] + (flg[m] ? pj1[c] : 0.f);
                float a0f, a1f;
                if (zside) { a0f = sigm(p0);  a1f = sigm(p1); }
                else       { a0f = tanha(p0); a1f = tanha(p1); }
                actp[c] = pack2(a0f, a1f);
            }
            ull oth[4];
#pragma unroll
            for (int c = 0; c < 4; c++)
                oth[c] = __shfl_xor_sync(0xffffffffu, actp[c], 16);
            if (zside) {
                float4 r0, r1;
                float* q0 = (float*)&r0;
                float* q1 = (float*)&r1;
#pragma unroll
                for (int c = 0; c < 4; c++) {
                    float2 z = u2f2(actp[c]);
                    float2 t = u2f2(oth[c]);
                    float2 sp = u2f2(mx[m * 128 + cc0 + c]);
                    q0[c] = fmaf(z.x, t.x - sp.x, sp.x);
                    q1[c] = fmaf(z.y, t.y - sp.y, sp.y);
                }
                *((float4*)(out_ns + (size_t)n * 64 + cc0)) = r0;
                *((float4*)(out_ns + ((size_t)NN + n) * 64 + cc0)) = r1;
            }
        }
        __syncwarp();
        n0 += cnt;
    }
}

// ---------------- K5: readout + policy heads ----------------
__global__ void readout_kernel(const float* __restrict__ ns,
                               const int* __restrict__ efferent_idx,
                               const float* __restrict__ W_dec,
                               const float* __restrict__ b_dec,
                               const float* __restrict__ W_mean,
                               const float* __restrict__ b_mean,
                               const float* __restrict__ W_ls,
                               const float* __restrict__ b_ls,
                               float* __restrict__ out) {
    __shared__ float ro[NB * HH];
    __shared__ float dec[NB * HH];
    int t = threadIdx.x;
    int b = t >> 6, h = t & 63;
    float sum = 0.f;
    for (int i = 0; i < NEFF; i++) {
        int idx = efferent_idx[i];
        sum += ns[((size_t)b * NN + idx) * HH + h];
    }
    ro[b * HH + h] = sum * (1.f / NEFF);
    __syncthreads();
    float acc = b_dec[h];
    for (int k = 0; k < HH; k++)
        acc += ro[b * HH + k] * W_dec[k * HH + h];
    dec[b * HH + h] = tanhf(acc);
    __syncthreads();
    if (t < NB * NA) {
        int bb = t / NA, a = t % NA;
        float m = b_mean[a], ls = b_ls[a];
        for (int k = 0; k < HH; k++) {
            float d = dec[bb * HH + k];
            m  += d * W_mean[k * NA + a];
            ls += d * W_ls[k * NA + a];
        }
        ls = fminf(fmaxf(ls, -5.f), 2.f);
        out[bb * NA + a] = m;
        out[NB * NA + bb * NA + a] = ls;
    }
}

// ---------------- launch ----------------
extern "C" void kernel_launch(void* const* d_in, const int* in_sizes, int n_in,
                              void* d_out, int out_size) {
    const float* obs    = (const float*)d_in[0];
    const float* state  = (const float*)d_in[1];
    const float* W_in   = (const float*)d_in[2];
    const float* b_in   = (const float*)d_in[3];
    const float* W_msg  = (const float*)d_in[4];
    const float* W_gate = (const float*)d_in[5];
    const float* b_gate = (const float*)d_in[6];
    const float* W_cand = (const float*)d_in[7];
    const float* b_cand = (const float*)d_in[8];
    const float* W_dec  = (const float*)d_in[9];
    const float* b_dec  = (const float*)d_in[10];
    const float* W_mean = (const float*)d_in[11];
    const float* b_mean = (const float*)d_in[12];
    const float* W_ls   = (const float*)d_in[13];
    const float* b_ls   = (const float*)d_in[14];
    const int* src_idx  = (const int*)d_in[15];
    const int* dst_idx  = (const int*)d_in[16];
    const int* aff_idx  = (const int*)d_in[17];
    const int* eff_idx  = (const int*)d_in[18];
    float* out = (float*)d_out;
    float* out_ns = out + 2 * NB * NA;

    prep_kernel<<<129, 128>>>(obs, W_in, b_in, W_msg, W_gate, W_cand, aff_idx);
    hist_kernel<<<(NE / 8 + 255) / 256, 256>>>((const int4*)dst_idx);
    scan_kernel<<<PB, 256>>>();

    size_t smem = 16384u * 4 + (size_t)NW * GROUP * 128 * 8 + (size_t)NW * WIN * 4;  // 200704
    cudaFuncSetAttribute(fused_kernel, cudaFuncAttributeMaxDynamicSharedMemorySize, (int)smem);
    fused_kernel<<<NBLK, NTHR, smem>>>((const int4*)src_idx, (const int4*)dst_idx,
                                       state, b_gate, b_cand, out_ns);

    readout_kernel<<<1, 128>>>(out_ns, eff_idx, W_dec, b_dec, W_mean, b_mean, W_ls, b_ls, out);
}

// round 15
// speedup vs baseline: 1.0299x; 1.0299x over previous
#include <cuda_runtime.h>
#include <cstdint>
#include <cstdio>

#define NB   2
#define NN   50000
#define HH   64
#define NE   1000000
#define NOBS 128
#define NA   18
#define NAFF 512
#define NEFF 256
#define PB   196

#define NBLK   148
#define NW     16
#define NTHR   512
#define WTOT   (NBLK * NW)     // 2368 warps
#define GROUP  6
#define WIN    512             // idx window (ints) per warp

// chunk split: NN = WTOT*21 + 272  ->  first 272 warps take 22 nodes
#define CHUNK_BIG   22
#define CHUNK_SMALL 21
#define NBIG        (NN - WTOT * CHUNK_SMALL)   // 272

typedef unsigned int u32;
typedef unsigned long long ull;

// ---------------- device scratch ----------------
__device__ float g_Wp[128 * 128];             // fused weight [k][c]
__device__ float g_projG[NB * HH];
__device__ float g_projC[NB * HH];
__device__ int   g_flag[NN];
__device__ int   g_cnt[NN];
__device__ int   g_off[NN + 1];
__device__ int   g_cur[NN];
__device__ int   g_esrc[NE + WIN];            // padded for cp.async overread
__device__ int   g_part[256];
__device__ unsigned g_sbar;                   // scan grid barrier

// ---------------- helpers ----------------
__device__ __forceinline__ void fma2(ull& d, ull a, ull b) {
    asm("fma.rn.f32x2 %0, %1, %2, %0;" : "+l"(d) : "l"(a), "l"(b));
}
__device__ __forceinline__ void add2(ull& d, ull a) {
    asm("add.rn.f32x2 %0, %0, %1;" : "+l"(d) : "l"(a));
}
__device__ __forceinline__ ull splat2(float w) {
    ull r; unsigned u = __float_as_uint(w);
    asm("mov.b64 %0, {%1, %1};" : "=l"(r) : "r"(u));
    return r;
}
__device__ __forceinline__ ull pack2(float a, float b) {
    ull r;
    asm("mov.b64 %0, {%1, %2};" : "=l"(r) : "r"(__float_as_uint(a)), "r"(__float_as_uint(b)));
    return r;
}
__device__ __forceinline__ float2 u2f2(ull v) {
    float2 f;
    f.x = __uint_as_float((unsigned)v);
    f.y = __uint_as_float((unsigned)(v >> 32));
    return f;
}
__device__ __forceinline__ void cpa16(void* dst, const void* src) {
    unsigned d = (unsigned)__cvta_generic_to_shared(dst);
    asm volatile("cp.async.cg.shared.global [%0], [%1], 16;" :: "r"(d), "l"(src));
}
__device__ __forceinline__ int warp_incl_scan(int v) {
    int lane = threadIdx.x & 31;
#pragma unroll
    for (int d = 1; d < 32; d <<= 1) {
        int t = __shfl_up_sync(0xffffffffu, v, d);
        if (lane >= d) v += t;
    }
    return v;
}
__device__ __forceinline__ float sigm(float x) { return __fdividef(1.f, 1.f + __expf(-x)); }
__device__ __forceinline__ float tanha(float x) { return 1.f - __fdividef(2.f, __expf(2.f * x) + 1.f); }

__device__ __forceinline__ void grid_barrier(unsigned* bar, unsigned expected) {
    __syncthreads();
    if (threadIdx.x == 0) {
        __threadfence();
        atomicAdd(bar, 1u);
        volatile unsigned* vb = bar;
        while (*vb < expected) { }
    }
    __syncthreads();
}

// ---------------- K1: merged prep (proj + flags + fused weight + zeroing) ----------------
__global__ void prep_kernel(const float* __restrict__ obs,
                            const float* __restrict__ W_in,
                            const float* __restrict__ b_in,
                            const float* __restrict__ W_msg,
                            const float* __restrict__ W_gate,
                            const float* __restrict__ W_cand,
                            const int* __restrict__ afferent_idx) {
    if (blockIdx.x == 128) {
        int t = threadIdx.x;
        if (t == 0) { g_sbar = 0u; }
        int4 z4 = make_int4(0, 0, 0, 0);
        for (int i = t; i < NN / 4; i += 128)
            ((int4*)g_flag)[i] = z4;
        __syncthreads();
        __shared__ float proj[NB * HH];
        int b = t >> 6, h = t & 63;
        float acc = b_in[h];
        for (int o = 0; o < NOBS; o++)
            acc += obs[b * NOBS + o] * W_in[o * HH + h];
        proj[b * HH + h] = acc;
        __syncthreads();
        float ag = 0.f, ac = 0.f;
        for (int k = 0; k < HH; k++) {
            float p = proj[b * HH + k];
            ag += p * W_gate[(HH + k) * HH + h];
            ac += p * W_cand[(HH + k) * HH + h];
        }
        g_projG[b * HH + h] = ag;
        g_projC[b * HH + h] = ac;
        for (int i = t; i < NAFF; i += 128)
            g_flag[afferent_idx[i]] = 1;
    } else {
        const int per = (NN + 127) / 128;   // 391
        int s = blockIdx.x * per;
        int e = s + per; if (e > NN) e = NN;
        for (int i = s + threadIdx.x; i < e; i += 128)
            g_cnt[i] = 0;
        int c = blockIdx.x;     // output column 0..127
        int k = threadIdx.x;    // input row 0..127
        float w;
        if (k < HH) {
            w = (c < HH) ? W_gate[k * HH + c] : W_cand[k * HH + (c - HH)];
        } else {
            int km = k - HH;
            float acc = 0.f;
            if (c < HH) {
                for (int t2 = 0; t2 < HH; t2++)
                    acc += W_msg[km * HH + t2] * W_gate[(HH + t2) * HH + c];
            } else {
                for (int t2 = 0; t2 < HH; t2++)
                    acc += W_msg[km * HH + t2] * W_cand[(HH + t2) * HH + (c - HH)];
            }
            w = acc;
        }
        g_Wp[k * 128 + c] = w;
    }
}

// ---------------- K2: histogram ----------------
__global__ void hist_kernel(const int4* __restrict__ dst4) {
    int i = (blockIdx.x * blockDim.x + threadIdx.x) * 2;
    if (i < NE / 4) {
        int4 d0 = __ldg(dst4 + i);
        int4 d1 = __ldg(dst4 + i + 1);
        atomicAdd(&g_cnt[d0.x], 1);
        atomicAdd(&g_cnt[d0.y], 1);
        atomicAdd(&g_cnt[d0.z], 1);
        atomicAdd(&g_cnt[d0.w], 1);
        atomicAdd(&g_cnt[d1.x], 1);
        atomicAdd(&g_cnt[d1.y], 1);
        atomicAdd(&g_cnt[d1.z], 1);
        atomicAdd(&g_cnt[d1.w], 1);
    }
}

// ---------------- K3: single-launch scan ----------------
__global__ void scan_kernel() {            // grid PB, 256 thr
    int b = blockIdx.x;
    int i = b * 256 + threadIdx.x;
    int t = threadIdx.x;
    int lane = t & 31, w = t >> 5;
    __shared__ int ws[8];
    __shared__ int blockBase;

    int v = (i < NN) ? g_cnt[i] : 0;

    int s = v;
#pragma unroll
    for (int d = 16; d > 0; d >>= 1) s += __shfl_down_sync(0xffffffffu, s, d);
    if (lane == 0) ws[w] = s;
    __syncthreads();
    if (t == 0) {
        int tot = 0;
        for (int x = 0; x < 8; x++) tot += ws[x];
        g_part[b] = tot;
    }
    grid_barrier(&g_sbar, PB);

    int pv = (t < PB && t < b) ? g_part[t] : 0;
#pragma unroll
    for (int d = 16; d > 0; d >>= 1) pv += __shfl_down_sync(0xffffffffu, pv, d);
    if (lane == 0) ws[w] = pv;
    __syncthreads();
    if (t == 0) {
        int bs = 0;
        for (int x = 0; x < 8; x++) bs += ws[x];
        blockBase = bs;
    }
    __syncthreads();

    int inc = warp_incl_scan(v);
    if (lane == 31) ws[w] = inc;
    __syncthreads();
    if (w == 0) {
        int qv = (lane < 8) ? ws[lane] : 0;
        int qi = warp_incl_scan(qv);
        if (lane < 8) ws[lane] = qi;
    }
    __syncthreads();
    int base = (w > 0) ? ws[w - 1] : 0;
    int off = blockBase + base + inc - v;
    if (i < NN) { g_off[i] = off; g_cur[i] = off; }
    if (i == 0) g_off[NN] = NE;
}

// ---------------- K4: scatter ----------------
__global__ void scatter_kernel(const int4* __restrict__ src4,
                               const int4* __restrict__ dst4) {
    int i = (blockIdx.x * blockDim.x + threadIdx.x) * 2;
    if (i < NE / 4) {
        int4 s0 = __ldg(src4 + i);
        int4 d0 = __ldg(dst4 + i);
        int4 s1 = __ldg(src4 + i + 1);
        int4 d1 = __ldg(dst4 + i + 1);
        g_esrc[atomicAdd(&g_cur[d0.x], 1)] = s0.x;
        g_esrc[atomicAdd(&g_cur[d0.y], 1)] = s0.y;
        g_esrc[atomicAdd(&g_cur[d0.z], 1)] = s0.z;
        g_esrc[atomicAdd(&g_cur[d0.w], 1)] = s0.w;
        g_esrc[atomicAdd(&g_cur[d1.x], 1)] = s1.x;
        g_esrc[atomicAdd(&g_cur[d1.y], 1)] = s1.y;
        g_esrc[atomicAdd(&g_cur[d1.z], 1)] = s1.z;
        g_esrc[atomicAdd(&g_cur[d1.w], 1)] = s1.w;
    }
}

// ---------------- K5: fused gather + f32x2 GEMM + GRU epilogue ----------------
// Gather: split-batch LDG.128, 12-deep unroll (12 loads in flight/warp) with
// 4-way split accumulator chains to break the add2 dependency chain.
__global__ void __launch_bounds__(NTHR, 1) fused_kernel(const float* __restrict__ state,
                                                        const float* __restrict__ b_gate,
                                                        const float* __restrict__ b_cand,
                                                        float* __restrict__ out_ns) {
    extern __shared__ float smem[];
    float* Ws = smem;                                    // 16384 floats
    ull* xs = (ull*)(smem + 16384);                      // NW * GROUP * 128 ull
    int* sIdx = (int*)(xs + NW * GROUP * 128);           // NW * WIN ints

    int tid = threadIdx.x;
    for (int i = tid; i < 4096; i += NTHR)
        ((float4*)Ws)[i] = ((const float4*)g_Wp)[i];
    __syncthreads();

    int warp = tid >> 5, lane = tid & 31;
    int q = lane & 15;
    int cc0 = q * 4;
    bool zside = lane < 16;
    int l4 = lane & 15;
    int half = lane >> 4;      // 0: batch0, 1: batch1

    float bias[4], pj0[4], pj1[4];
#pragma unroll
    for (int c = 0; c < 4; c++) {
        int cc = cc0 + c;
        if (zside) { bias[c] = __ldg(b_gate + cc); pj0[c] = g_projG[cc]; pj1[c] = g_projG[64 + cc]; }
        else       { bias[c] = __ldg(b_cand + cc); pj0[c] = g_projC[cc]; pj1[c] = g_projC[64 + cc]; }
    }

    ull* mx = xs + warp * (GROUP * 128);
    int* widx = sIdx + warp * WIN;
    int gwid = blockIdx.x * NW + warp;
    const ulonglong2* U2 = (const ulonglong2*)state + (size_t)half * NN * 16;

    int cBase, cCnt;
    if (gwid < NBIG) { cBase = gwid * CHUNK_BIG; cCnt = CHUNK_BIG; }
    else             { cBase = NBIG * CHUNK_BIG + (gwid - NBIG) * CHUNK_SMALL; cCnt = CHUNK_SMALL; }
    int nEnd = cBase + cCnt;

    // stage index window for the chunk
    int slab = __ldg(&g_off[cBase]) & ~3;
    for (int c = lane; c < WIN / 4; c += 32)
        cpa16(widx + c * 4, g_esrc + slab + c * 4);
    asm volatile("cp.async.commit_group;" ::: "memory");
    asm volatile("cp.async.wait_group 0;" ::: "memory");
    __syncwarp();

    int sg = 1 + (gwid % GROUP);       // staggered first sub-group size
    int n0 = cBase;
    while (n0 < nEnd) {
        int cnt = nEnd - n0;
        if (cnt > sg) cnt = sg;
        sg = GROUP;
        int flg[GROUP];

        // ---- gather phase: 12-deep MLP, 4-way chains ----
        for (int m = 0; m < cnt; m++) {
            int n = n0 + m;
            int beg = __ldg(&g_off[n]), end = __ldg(&g_off[n + 1]);
            flg[m] = __ldg(&g_flag[n]);
            ull cA[4] = {0ull, 0ull, 0ull, 0ull};
            ull cB[4] = {0ull, 0ull, 0ull, 0ull};
            int j = beg;
            while (j < end) {
                if (j >= slab + WIN) {           // refill window (rare)
                    slab = j & ~3;
                    for (int c = lane; c < WIN / 4; c += 32)
                        cpa16(widx + c * 4, g_esrc + slab + c * 4);
                    asm volatile("cp.async.commit_group;" ::: "memory");
                    asm volatile("cp.async.wait_group 0;" ::: "memory");
                    __syncwarp();
                }
                int lim = slab + WIN;
                if (lim > end) lim = end;
                for (; j + 12 <= lim; j += 12) {
                    int e[12];
#pragma unroll
                    for (int u = 0; u < 12; u++) e[u] = widx[j - slab + u];
                    ulonglong2 v[12];
#pragma unroll
                    for (int u = 0; u < 12; u++)
                        v[u] = __ldg(U2 + (size_t)e[u] * 16 + l4);
#pragma unroll
                    for (int u = 0; u < 12; u++) {
                        add2(cA[u & 3], v[u].x);
                        add2(cB[u & 3], v[u].y);
                    }
                }
                for (; j < lim; j++) {
                    int e0 = widx[j - slab];
                    ulonglong2 v0 = __ldg(U2 + (size_t)e0 * 16 + l4);
                    add2(cA[0], v0.x);
                    add2(cB[0], v0.y);
                }
            }
            // merge chains
            add2(cA[0], cA[1]); add2(cA[2], cA[3]); add2(cA[0], cA[2]);
            add2(cB[0], cB[1]); add2(cB[2], cB[3]); add2(cB[0], cB[2]);
            ull a0 = cA[0], a1 = cB[0];

            ulonglong2 so = __ldg(U2 + (size_t)n * 16 + l4);
            ull po0 = __shfl_xor_sync(0xffffffffu, so.x, 16);
            ull po1 = __shfl_xor_sync(0xffffffffu, so.y, 16);
            ull qa0 = __shfl_xor_sync(0xffffffffu, a0, 16);
            ull qa1 = __shfl_xor_sync(0xffffffffu, a1, 16);
            ull* row = mx + m * 128;
            if (lane < 16) {
                float2 o0 = u2f2(so.x), o1 = u2f2(so.y);   // b0 state
                float2 p0 = u2f2(po0),  p1 = u2f2(po1);    // b1 state
                ((float4*)row)[2 * l4]     = make_float4(o0.x, p0.x, o0.y, p0.y);
                ((float4*)row)[2 * l4 + 1] = make_float4(o1.x, p1.x, o1.y, p1.y);
            } else {
                float2 o0 = u2f2(a0),  o1 = u2f2(a1);      // b1 agg
                float2 p0 = u2f2(qa0), p1 = u2f2(qa1);     // b0 agg
                ((float4*)(row + 64))[2 * l4]     = make_float4(p0.x, o0.x, p0.y, o0.y);
                ((float4*)(row + 64))[2 * l4 + 1] = make_float4(p1.x, o1.x, p1.y, o1.y);
            }
        }
        __syncwarp();

        // ---- FMA phase (batch-paired, splat weights) ----
        ull acc6[GROUP][4];
#pragma unroll
        for (int m = 0; m < GROUP; m++)
#pragma unroll
            for (int c = 0; c < 4; c++) acc6[m][c] = 0ull;

#pragma unroll 4
        for (int k = 0; k < 128; k += 2) {
            float4 wA = ((const float4*)(Ws + k * 128))[lane];
            float4 wB = ((const float4*)(Ws + (k + 1) * 128))[lane];
            ull wa0 = splat2(wA.x), wa1 = splat2(wA.y), wa2 = splat2(wA.z), wa3 = splat2(wA.w);
            ull wb0 = splat2(wB.x), wb1 = splat2(wB.y), wb2 = splat2(wB.z), wb3 = splat2(wB.w);
#pragma unroll
            for (int m = 0; m < GROUP; m++) {
                ulonglong2 xv = ((const ulonglong2*)(mx + m * 128))[k >> 1];
                fma2(acc6[m][0], wa0, xv.x); fma2(acc6[m][1], wa1, xv.x);
                fma2(acc6[m][2], wa2, xv.x); fma2(acc6[m][3], wa3, xv.x);
                fma2(acc6[m][0], wb0, xv.y); fma2(acc6[m][1], wb1, xv.y);
                fma2(acc6[m][2], wb2, xv.y); fma2(acc6[m][3], wb3, xv.y);
            }
        }

        // ---- epilogue ----
        for (int m = 0; m < cnt; m++) {
            int n = n0 + m;
            ull actp[4];
#pragma unroll
            for (int c = 0; c < 4; c++) {
                float2 pre = u2f2(acc6[m][c]);
                float p0 = pre.x + bias[c] + (flg[m] ? pj0[c] : 0.f);
                float p1 = pre.y + bias[c] + (flg[m] ? pj1[c] : 0.f);
                float a0f, a1f;
                if (zside) { a0f = sigm(p0);  a1f = sigm(p1); }
                else       { a0f = tanha(p0); a1f = tanha(p1); }
                actp[c] = pack2(a0f, a1f);
            }
            ull oth[4];
#pragma unroll
            for (int c = 0; c < 4; c++)
                oth[c] = __shfl_xor_sync(0xffffffffu, actp[c], 16);
            if (zside) {
                float4 r0, r1;
                float* q0 = (float*)&r0;
                float* q1 = (float*)&r1;
#pragma unroll
                for (int c = 0; c < 4; c++) {
                    float2 z = u2f2(actp[c]);
                    float2 t = u2f2(oth[c]);
                    float2 sp = u2f2(mx[m * 128 + cc0 + c]);
                    q0[c] = fmaf(z.x, t.x - sp.x, sp.x);
                    q1[c] = fmaf(z.y, t.y - sp.y, sp.y);
                }
                *((float4*)(out_ns + (size_t)n * 64 + cc0)) = r0;
                *((float4*)(out_ns + ((size_t)NN + n) * 64 + cc0)) = r1;
            }
        }
        __syncwarp();
        n0 += cnt;
    }
}

// ---------------- K6: readout + policy heads ----------------
__global__ void readout_kernel(const float* __restrict__ ns,
                               const int* __restrict__ efferent_idx,
                               const float* __restrict__ W_dec,
                               const float* __restrict__ b_dec,
                               const float* __restrict__ W_mean,
                               const float* __restrict__ b_mean,
                               const float* __restrict__ W_ls,
                               const float* __restrict__ b_ls,
                               float* __restrict__ out) {
    __shared__ float ro[NB * HH];
    __shared__ float dec[NB * HH];
    int t = threadIdx.x;
    int b = t >> 6, h = t & 63;
    float sum = 0.f;
    for (int i = 0; i < NEFF; i++) {
        int idx = efferent_idx[i];
        sum += ns[((size_t)b * NN + idx) * HH + h];
    }
    ro[b * HH + h] = sum * (1.f / NEFF);
    __syncthreads();
    float acc = b_dec[h];
    for (int k = 0; k < HH; k++)
        acc += ro[b * HH + k] * W_dec[k * HH + h];
    dec[b * HH + h] = tanhf(acc);
    __syncthreads();
    if (t < NB * NA) {
        int bb = t / NA, a = t % NA;
        float m = b_mean[a], ls = b_ls[a];
        for (int k = 0; k < HH; k++) {
            float d = dec[bb * HH + k];
            m  += d * W_mean[k * NA + a];
            ls += d * W_ls[k * NA + a];
        }
        ls = fminf(fmaxf(ls, -5.f), 2.f);
        out[bb * NA + a] = m;
        out[NB * NA + bb * NA + a] = ls;
    }
}

// ---------------- launch ----------------
extern "C" void kernel_launch(void* const* d_in, const int* in_sizes, int n_in,
                              void* d_out, int out_size) {
    const float* obs    = (const float*)d_in[0];
    const float* state  = (const float*)d_in[1];
    const float* W_in   = (const float*)d_in[2];
    const float* b_in   = (const float*)d_in[3];
    const float* W_msg  = (const float*)d_in[4];
    const float* W_gate = (const float*)d_in[5];
    const float* b_gate = (const float*)d_in[6];
    const float* W_cand = (const float*)d_in[7];
    const float* b_cand = (const float*)d_in[8];
    const float* W_dec  = (const float*)d_in[9];
    const float* b_dec  = (const float*)d_in[10];
    const float* W_mean = (const float*)d_in[11];
    const float* b_mean = (const float*)d_in[12];
    const float* W_ls   = (const float*)d_in[13];
    const float* b_ls   = (const float*)d_in[14];
    const int* src_idx  = (const int*)d_in[15];
    const int* dst_idx  = (const int*)d_in[16];
    const int* aff_idx  = (const int*)d_in[17];
    const int* eff_idx  = (const int*)d_in[18];
    float* out = (float*)d_out;
    float* out_ns = out + 2 * NB * NA;

    prep_kernel<<<129, 128>>>(obs, W_in, b_in, W_msg, W_gate, W_cand, aff_idx);
    hist_kernel<<<(NE / 8 + 255) / 256, 256>>>((const int4*)dst_idx);
    scan_kernel<<<PB, 256>>>();
    scatter_kernel<<<(NE / 8 + 255) / 256, 256>>>((const int4*)src_idx, (const int4*)dst_idx);

    size_t smem = 16384u * 4 + (size_t)NW * GROUP * 128 * 8 + (size_t)NW * WIN * 4;  // 196608
    cudaFuncSetAttribute(fused_kernel, cudaFuncAttributeMaxDynamicSharedMemorySize, (int)smem);
    fused_kernel<<<NBLK, NTHR, smem>>>(state, b_gate, b_cand, out_ns);

    readout_kernel<<<1, 128>>>(out_ns, eff_idx, W_dec, b_dec, W_mean, b_mean, W_ls, b_ls, out);
}

// round 16
// speedup vs baseline: 1.0553x; 1.0246x over previous
#include <cuda_runtime.h>
#include <cstdint>
#include <cstdio>

#define NB   2
#define NN   50000
#define HH   64
#define NE   1000000
#define NOBS 128
#define NA   18
#define NAFF 512
#define NEFF 256
#define PB   196

#define NBLK   148
#define NW     16
#define NTHR   512
#define WTOT   (NBLK * NW)     // 2368 warps
#define GROUP  6
#define WIN    512             // idx window (ints) per warp

// chunk split: NN = WTOT*21 + 272  ->  first 272 warps take 22 nodes
#define CHUNK_BIG   22
#define CHUNK_SMALL 21
#define NBIG        (NN - WTOT * CHUNK_SMALL)   // 272

typedef unsigned int u32;
typedef unsigned long long ull;

// ---------------- device scratch ----------------
__device__ float g_Wp[128 * 128];             // fused weight [k][c]
__device__ float g_projG[NB * HH];
__device__ float g_projC[NB * HH];
__device__ int   g_flag[NN];
__device__ int   g_cnt[NN];
__device__ int   g_off[NN + 1];
__device__ int   g_cur[NN];
__device__ int   g_esrc[NE + WIN];            // padded for cp.async overread
__device__ int   g_part[256];
__device__ unsigned g_sbar;                   // scan grid barrier

// ---------------- helpers ----------------
__device__ __forceinline__ void fma2(ull& d, ull a, ull b) {
    asm("fma.rn.f32x2 %0, %1, %2, %0;" : "+l"(d) : "l"(a), "l"(b));
}
__device__ __forceinline__ void add2(ull& d, ull a) {
    asm("add.rn.f32x2 %0, %0, %1;" : "+l"(d) : "l"(a));
}
__device__ __forceinline__ ull splat2(float w) {
    ull r; unsigned u = __float_as_uint(w);
    asm("mov.b64 %0, {%1, %1};" : "=l"(r) : "r"(u));
    return r;
}
__device__ __forceinline__ ull pack2(float a, float b) {
    ull r;
    asm("mov.b64 %0, {%1, %2};" : "=l"(r) : "r"(__float_as_uint(a)), "r"(__float_as_uint(b)));
    return r;
}
__device__ __forceinline__ float2 u2f2(ull v) {
    float2 f;
    f.x = __uint_as_float((unsigned)v);
    f.y = __uint_as_float((unsigned)(v >> 32));
    return f;
}
__device__ __forceinline__ void cpa16(void* dst, const void* src) {
    unsigned d = (unsigned)__cvta_generic_to_shared(dst);
    asm volatile("cp.async.cg.shared.global [%0], [%1], 16;" :: "r"(d), "l"(src));
}
__device__ __forceinline__ int warp_incl_scan(int v) {
    int lane = threadIdx.x & 31;
#pragma unroll
    for (int d = 1; d < 32; d <<= 1) {
        int t = __shfl_up_sync(0xffffffffu, v, d);
        if (lane >= d) v += t;
    }
    return v;
}
__device__ __forceinline__ float sigm(float x) { return __fdividef(1.f, 1.f + __expf(-x)); }
__device__ __forceinline__ float tanha(float x) { return 1.f - __fdividef(2.f, __expf(2.f * x) + 1.f); }

__device__ __forceinline__ void grid_barrier(unsigned* bar, unsigned expected) {
    __syncthreads();
    if (threadIdx.x == 0) {
        __threadfence();
        atomicAdd(bar, 1u);
        volatile unsigned* vb = bar;
        while (*vb < expected) { }
    }
    __syncthreads();
}

// ---------------- K1: merged prep (proj + flags + fused weight + zeroing) ----------------
__global__ void prep_kernel(const float* __restrict__ obs,
                            const float* __restrict__ W_in,
                            const float* __restrict__ b_in,
                            const float* __restrict__ W_msg,
                            const float* __restrict__ W_gate,
                            const float* __restrict__ W_cand,
                            const int* __restrict__ afferent_idx) {
    if (blockIdx.x == 128) {
        int t = threadIdx.x;
        if (t == 0) { g_sbar = 0u; }
        int4 z4 = make_int4(0, 0, 0, 0);
        for (int i = t; i < NN / 4; i += 128)
            ((int4*)g_flag)[i] = z4;
        __syncthreads();
        __shared__ float proj[NB * HH];
        int b = t >> 6, h = t & 63;
        float acc = b_in[h];
        for (int o = 0; o < NOBS; o++)
            acc += obs[b * NOBS + o] * W_in[o * HH + h];
        proj[b * HH + h] = acc;
        __syncthreads();
        float ag = 0.f, ac = 0.f;
        for (int k = 0; k < HH; k++) {
            float p = proj[b * HH + k];
            ag += p * W_gate[(HH + k) * HH + h];
            ac += p * W_cand[(HH + k) * HH + h];
        }
        g_projG[b * HH + h] = ag;
        g_projC[b * HH + h] = ac;
        for (int i = t; i < NAFF; i += 128)
            g_flag[afferent_idx[i]] = 1;
    } else {
        const int per = (NN + 127) / 128;   // 391
        int s = blockIdx.x * per;
        int e = s + per; if (e > NN) e = NN;
        for (int i = s + threadIdx.x; i < e; i += 128)
            g_cnt[i] = 0;
        int c = blockIdx.x;     // output column 0..127
        int k = threadIdx.x;    // input row 0..127
        float w;
        if (k < HH) {
            w = (c < HH) ? W_gate[k * HH + c] : W_cand[k * HH + (c - HH)];
        } else {
            int km = k - HH;
            float acc = 0.f;
            if (c < HH) {
                for (int t2 = 0; t2 < HH; t2++)
                    acc += W_msg[km * HH + t2] * W_gate[(HH + t2) * HH + c];
            } else {
                for (int t2 = 0; t2 < HH; t2++)
                    acc += W_msg[km * HH + t2] * W_cand[(HH + t2) * HH + (c - HH)];
            }
            w = acc;
        }
        g_Wp[k * 128 + c] = w;
    }
}

// ---------------- K2: histogram (4x int4 per thread, 16 atomics in flight) ----------------
__global__ void hist_kernel(const int4* __restrict__ dst4) {
    int i = (blockIdx.x * blockDim.x + threadIdx.x) * 4;
    if (i + 3 < NE / 4) {
        int4 d0 = __ldg(dst4 + i);
        int4 d1 = __ldg(dst4 + i + 1);
        int4 d2 = __ldg(dst4 + i + 2);
        int4 d3 = __ldg(dst4 + i + 3);
        atomicAdd(&g_cnt[d0.x], 1); atomicAdd(&g_cnt[d0.y], 1);
        atomicAdd(&g_cnt[d0.z], 1); atomicAdd(&g_cnt[d0.w], 1);
        atomicAdd(&g_cnt[d1.x], 1); atomicAdd(&g_cnt[d1.y], 1);
        atomicAdd(&g_cnt[d1.z], 1); atomicAdd(&g_cnt[d1.w], 1);
        atomicAdd(&g_cnt[d2.x], 1); atomicAdd(&g_cnt[d2.y], 1);
        atomicAdd(&g_cnt[d2.z], 1); atomicAdd(&g_cnt[d2.w], 1);
        atomicAdd(&g_cnt[d3.x], 1); atomicAdd(&g_cnt[d3.y], 1);
        atomicAdd(&g_cnt[d3.z], 1); atomicAdd(&g_cnt[d3.w], 1);
    } else if (i < NE / 4) {
        for (int j = i; j < NE / 4; j++) {
            int4 d = __ldg(dst4 + j);
            atomicAdd(&g_cnt[d.x], 1); atomicAdd(&g_cnt[d.y], 1);
            atomicAdd(&g_cnt[d.z], 1); atomicAdd(&g_cnt[d.w], 1);
        }
    }
}

// ---------------- K3: single-launch scan ----------------
__global__ void scan_kernel() {            // grid PB, 256 thr
    int b = blockIdx.x;
    int i = b * 256 + threadIdx.x;
    int t = threadIdx.x;
    int lane = t & 31, w = t >> 5;
    __shared__ int ws[8];
    __shared__ int blockBase;

    int v = (i < NN) ? g_cnt[i] : 0;

    int s = v;
#pragma unroll
    for (int d = 16; d > 0; d >>= 1) s += __shfl_down_sync(0xffffffffu, s, d);
    if (lane == 0) ws[w] = s;
    __syncthreads();
    if (t == 0) {
        int tot = 0;
        for (int x = 0; x < 8; x++) tot += ws[x];
        g_part[b] = tot;
    }
    grid_barrier(&g_sbar, PB);

    int pv = (t < PB && t < b) ? g_part[t] : 0;
#pragma unroll
    for (int d = 16; d > 0; d >>= 1) pv += __shfl_down_sync(0xffffffffu, pv, d);
    if (lane == 0) ws[w] = pv;
    __syncthreads();
    if (t == 0) {
        int bs = 0;
        for (int x = 0; x < 8; x++) bs += ws[x];
        blockBase = bs;
    }
    __syncthreads();

    int inc = warp_incl_scan(v);
    if (lane == 31) ws[w] = inc;
    __syncthreads();
    if (w == 0) {
        int qv = (lane < 8) ? ws[lane] : 0;
        int qi = warp_incl_scan(qv);
        if (lane < 8) ws[lane] = qi;
    }
    __syncthreads();
    int base = (w > 0) ? ws[w - 1] : 0;
    int off = blockBase + base + inc - v;
    if (i < NN) { g_off[i] = off; g_cur[i] = off; }
    if (i == 0) g_off[NN] = NE;
}

// ---------------- K4: scatter (4x int4 per thread, 16 atomics in flight) ----------------
__global__ void scatter_kernel(const int4* __restrict__ src4,
                               const int4* __restrict__ dst4) {
    int i = (blockIdx.x * blockDim.x + threadIdx.x) * 4;
    if (i + 3 < NE / 4) {
        int4 s0 = __ldg(src4 + i),     d0 = __ldg(dst4 + i);
        int4 s1 = __ldg(src4 + i + 1), d1 = __ldg(dst4 + i + 1);
        int4 s2 = __ldg(src4 + i + 2), d2 = __ldg(dst4 + i + 2);
        int4 s3 = __ldg(src4 + i + 3), d3 = __ldg(dst4 + i + 3);
        int p0 = atomicAdd(&g_cur[d0.x], 1), p1 = atomicAdd(&g_cur[d0.y], 1);
        int p2 = atomicAdd(&g_cur[d0.z], 1), p3 = atomicAdd(&g_cur[d0.w], 1);
        int p4 = atomicAdd(&g_cur[d1.x], 1), p5 = atomicAdd(&g_cur[d1.y], 1);
        int p6 = atomicAdd(&g_cur[d1.z], 1), p7 = atomicAdd(&g_cur[d1.w], 1);
        int p8 = atomicAdd(&g_cur[d2.x], 1), p9 = atomicAdd(&g_cur[d2.y], 1);
        int pa = atomicAdd(&g_cur[d2.z], 1), pb = atomicAdd(&g_cur[d2.w], 1);
        int pc = atomicAdd(&g_cur[d3.x], 1), pd = atomicAdd(&g_cur[d3.y], 1);
        int pe = atomicAdd(&g_cur[d3.z], 1), pf = atomicAdd(&g_cur[d3.w], 1);
        g_esrc[p0] = s0.x; g_esrc[p1] = s0.y; g_esrc[p2] = s0.z; g_esrc[p3] = s0.w;
        g_esrc[p4] = s1.x; g_esrc[p5] = s1.y; g_esrc[p6] = s1.z; g_esrc[p7] = s1.w;
        g_esrc[p8] = s2.x; g_esrc[p9] = s2.y; g_esrc[pa] = s2.z; g_esrc[pb] = s2.w;
        g_esrc[pc] = s3.x; g_esrc[pd] = s3.y; g_esrc[pe] = s3.z; g_esrc[pf] = s3.w;
    } else if (i < NE / 4) {
        for (int j = i; j < NE / 4; j++) {
            int4 s = __ldg(src4 + j);
            int4 d = __ldg(dst4 + j);
            g_esrc[atomicAdd(&g_cur[d.x], 1)] = s.x;
            g_esrc[atomicAdd(&g_cur[d.y], 1)] = s.y;
            g_esrc[atomicAdd(&g_cur[d.z], 1)] = s.z;
            g_esrc[atomicAdd(&g_cur[d.w], 1)] = s.w;
        }
    }
}

// ---------------- K5: fused gather + f32x2 GEMM + GRU epilogue (R12 proven form) ----------------
__global__ void __launch_bounds__(NTHR, 1) fused_kernel(const float* __restrict__ state,
                                                        const float* __restrict__ b_gate,
                                                        const float* __restrict__ b_cand,
                                                        float* __restrict__ out_ns) {
    extern __shared__ float smem[];
    float* Ws = smem;                                    // 16384 floats
    ull* xs = (ull*)(smem + 16384);                      // NW * GROUP * 128 ull
    int* sIdx = (int*)(xs + NW * GROUP * 128);           // NW * WIN ints

    int tid = threadIdx.x;
    for (int i = tid; i < 4096; i += NTHR)
        ((float4*)Ws)[i] = ((const float4*)g_Wp)[i];
    __syncthreads();

    int warp = tid >> 5, lane = tid & 31;
    int q = lane & 15;
    int cc0 = q * 4;
    bool zside = lane < 16;
    int l4 = lane & 15;
    int half = lane >> 4;      // 0: batch0, 1: batch1

    float bias[4], pj0[4], pj1[4];
#pragma unroll
    for (int c = 0; c < 4; c++) {
        int cc = cc0 + c;
        if (zside) { bias[c] = __ldg(b_gate + cc); pj0[c] = g_projG[cc]; pj1[c] = g_projG[64 + cc]; }
        else       { bias[c] = __ldg(b_cand + cc); pj0[c] = g_projC[cc]; pj1[c] = g_projC[64 + cc]; }
    }

    ull* mx = xs + warp * (GROUP * 128);
    int* widx = sIdx + warp * WIN;
    int gwid = blockIdx.x * NW + warp;
    const ulonglong2* U2 = (const ulonglong2*)state + (size_t)half * NN * 16;

    int cBase, cCnt;
    if (gwid < NBIG) { cBase = gwid * CHUNK_BIG; cCnt = CHUNK_BIG; }
    else             { cBase = NBIG * CHUNK_BIG + (gwid - NBIG) * CHUNK_SMALL; cCnt = CHUNK_SMALL; }
    int nEnd = cBase + cCnt;

    // stage index window for the chunk
    int slab = __ldg(&g_off[cBase]) & ~3;
    for (int c = lane; c < WIN / 4; c += 32)
        cpa16(widx + c * 4, g_esrc + slab + c * 4);
    asm volatile("cp.async.commit_group;" ::: "memory");
    asm volatile("cp.async.wait_group 0;" ::: "memory");
    __syncwarp();

    int sg = 1 + (gwid % GROUP);       // staggered first sub-group size
    int n0 = cBase;
    while (n0 < nEnd) {
        int cnt = nEnd - n0;
        if (cnt > sg) cnt = sg;
        sg = GROUP;
        int flg[GROUP];

        // ---- gather phase (split-batch LDG.128 + f32x2 accumulate, 8-unroll) ----
        for (int m = 0; m < cnt; m++) {
            int n = n0 + m;
            int beg = __ldg(&g_off[n]), end = __ldg(&g_off[n + 1]);
            flg[m] = __ldg(&g_flag[n]);
            ull a0 = 0ull, a1 = 0ull;
            int j = beg;
            while (j < end) {
                if (j >= slab + WIN) {           // refill window (rare)
                    slab = j & ~3;
                    for (int c = lane; c < WIN / 4; c += 32)
                        cpa16(widx + c * 4, g_esrc + slab + c * 4);
                    asm volatile("cp.async.commit_group;" ::: "memory");
                    asm volatile("cp.async.wait_group 0;" ::: "memory");
                    __syncwarp();
                }
                int lim = slab + WIN;
                if (lim > end) lim = end;
                for (; j + 8 <= lim; j += 8) {
                    int e[8];
#pragma unroll
                    for (int u = 0; u < 8; u++) e[u] = widx[j - slab + u];
                    ulonglong2 v[8];
#pragma unroll
                    for (int u = 0; u < 8; u++)
                        v[u] = __ldg(U2 + (size_t)e[u] * 16 + l4);
#pragma unroll
                    for (int u = 0; u < 8; u++) {
                        add2(a0, v[u].x);
                        add2(a1, v[u].y);
                    }
                }
                for (; j < lim; j++) {
                    int e0 = widx[j - slab];
                    ulonglong2 v0 = __ldg(U2 + (size_t)e0 * 16 + l4);
                    add2(a0, v0.x);
                    add2(a1, v0.y);
                }
            }
            ulonglong2 so = __ldg(U2 + (size_t)n * 16 + l4);
            ull po0 = __shfl_xor_sync(0xffffffffu, so.x, 16);
            ull po1 = __shfl_xor_sync(0xffffffffu, so.y, 16);
            ull qa0 = __shfl_xor_sync(0xffffffffu, a0, 16);
            ull qa1 = __shfl_xor_sync(0xffffffffu, a1, 16);
            ull* row = mx + m * 128;
            if (lane < 16) {
                float2 o0 = u2f2(so.x), o1 = u2f2(so.y);   // b0 state
                float2 p0 = u2f2(po0),  p1 = u2f2(po1);    // b1 state
                ((float4*)row)[2 * l4]     = make_float4(o0.x, p0.x, o0.y, p0.y);
                ((float4*)row)[2 * l4 + 1] = make_float4(o1.x, p1.x, o1.y, p1.y);
            } else {
                float2 o0 = u2f2(a0),  o1 = u2f2(a1);      // b1 agg
                float2 p0 = u2f2(qa0), p1 = u2f2(qa1);     // b0 agg
                ((float4*)(row + 64))[2 * l4]     = make_float4(p0.x, o0.x, p0.y, o0.y);
                ((float4*)(row + 64))[2 * l4 + 1] = make_float4(p1.x, o1.x, p1.y, o1.y);
            }
        }
        __syncwarp();

        // ---- FMA phase (batch-paired, splat weights) ----
        ull acc6[GROUP][4];
#pragma unroll
        for (int m = 0; m < GROUP; m++)
#pragma unroll
            for (int c = 0; c < 4; c++) acc6[m][c] = 0ull;

#pragma unroll 4
        for (int k = 0; k < 128; k += 2) {
            float4 wA = ((const float4*)(Ws + k * 128))[lane];
            float4 wB = ((const float4*)(Ws + (k + 1) * 128))[lane];
            ull wa0 = splat2(wA.x), wa1 = splat2(wA.y), wa2 = splat2(wA.z), wa3 = splat2(wA.w);
            ull wb0 = splat2(wB.x), wb1 = splat2(wB.y), wb2 = splat2(wB.z), wb3 = splat2(wB.w);
#pragma unroll
            for (int m = 0; m < GROUP; m++) {
                ulonglong2 xv = ((const ulonglong2*)(mx + m * 128))[k >> 1];
                fma2(acc6[m][0], wa0, xv.x); fma2(acc6[m][1], wa1, xv.x);
                fma2(acc6[m][2], wa2, xv.x); fma2(acc6[m][3], wa3, xv.x);
                fma2(acc6[m][0], wb0, xv.y); fma2(acc6[m][1], wb1, xv.y);
                fma2(acc6[m][2], wb2, xv.y); fma2(acc6[m][3], wb3, xv.y);
            }
        }

        // ---- epilogue ----
        for (int m = 0; m < cnt; m++) {
            int n = n0 + m;
            ull actp[4];
#pragma unroll
            for (int c = 0; c < 4; c++) {
                float2 pre = u2f2(acc6[m][c]);
                float p0 = pre.x + bias[c] + (flg[m] ? pj0[c] : 0.f);
                float p1 = pre.y + bias[c] + (flg[m] ? pj1[c] : 0.f);
                float a0f, a1f;
                if (zside) { a0f = sigm(p0);  a1f = sigm(p1); }
                else       { a0f = tanha(p0); a1f = tanha(p1); }
                actp[c] = pack2(a0f, a1f);
            }
            ull oth[4];
#pragma unroll
            for (int c = 0; c < 4; c++)
                oth[c] = __shfl_xor_sync(0xffffffffu, actp[c], 16);
            if (zside) {
                float4 r0, r1;
                float* q0 = (float*)&r0;
                float* q1 = (float*)&r1;
#pragma unroll
                for (int c = 0; c < 4; c++) {
                    float2 z = u2f2(actp[c]);
                    float2 t = u2f2(oth[c]);
                    float2 sp = u2f2(mx[m * 128 + cc0 + c]);
                    q0[c] = fmaf(z.x, t.x - sp.x, sp.x);
                    q1[c] = fmaf(z.y, t.y - sp.y, sp.y);
                }
                *((float4*)(out_ns + (size_t)n * 64 + cc0)) = r0;
                *((float4*)(out_ns + ((size_t)NN + n) * 64 + cc0)) = r1;
            }
        }
        __syncwarp();
        n0 += cnt;
    }
}

// ---------------- K6: readout + policy heads ----------------
__global__ void readout_kernel(const float* __restrict__ ns,
                               const int* __restrict__ efferent_idx,
                               const float* __restrict__ W_dec,
                               const float* __restrict__ b_dec,
                               const float* __restrict__ W_mean,
                               const float* __restrict__ b_mean,
                               const float* __restrict__ W_ls,
                               const float* __restrict__ b_ls,
                               float* __restrict__ out) {
    __shared__ float ro[NB * HH];
    __shared__ float dec[NB * HH];
    int t = threadIdx.x;
    int b = t >> 6, h = t & 63;
    float sum = 0.f;
    for (int i = 0; i < NEFF; i++) {
        int idx = efferent_idx[i];
        sum += ns[((size_t)b * NN + idx) * HH + h];
    }
    ro[b * HH + h] = sum * (1.f / NEFF);
    __syncthreads();
    float acc = b_dec[h];
    for (int k = 0; k < HH; k++)
        acc += ro[b * HH + k] * W_dec[k * HH + h];
    dec[b * HH + h] = tanhf(acc);
    __syncthreads();
    if (t < NB * NA) {
        int bb = t / NA, a = t % NA;
        float m = b_mean[a], ls = b_ls[a];
        for (int k = 0; k < HH; k++) {
            float d = dec[bb * HH + k];
            m  += d * W_mean[k * NA + a];
            ls += d * W_ls[k * NA + a];
        }
        ls = fminf(fmaxf(ls, -5.f), 2.f);
        out[bb * NA + a] = m;
        out[NB * NA + bb * NA + a] = ls;
    }
}

// ---------------- launch ----------------
extern "C" void kernel_launch(void* const* d_in, const int* in_sizes, int n_in,
                              void* d_out, int out_size) {
    const float* obs    = (const float*)d_in[0];
    const float* state  = (const float*)d_in[1];
    const float* W_in   = (const float*)d_in[2];
    const float* b_in   = (const float*)d_in[3];
    const float* W_msg  = (const float*)d_in[4];
    const float* W_gate = (const float*)d_in[5];
    const float* b_gate = (const float*)d_in[6];
    const float* W_cand = (const float*)d_in[7];
    const float* b_cand = (const float*)d_in[8];
    const float* W_dec  = (const float*)d_in[9];
    const float* b_dec  = (const float*)d_in[10];
    const float* W_mean = (const float*)d_in[11];
    const float* b_mean = (const float*)d_in[12];
    const float* W_ls   = (const float*)d_in[13];
    const float* b_ls   = (const float*)d_in[14];
    const int* src_idx  = (const int*)d_in[15];
    const int* dst_idx  = (const int*)d_in[16];
    const int* aff_idx  = (const int*)d_in[17];
    const int* eff_idx  = (const int*)d_in[18];
    float* out = (float*)d_out;
    float* out_ns = out + 2 * NB * NA;

    prep_kernel<<<129, 128>>>(obs, W_in, b_in, W_msg, W_gate, W_cand, aff_idx);
    hist_kernel<<<(NE / 16 + 255) / 256, 256>>>((const int4*)dst_idx);
    scan_kernel<<<PB, 256>>>();
    scatter_kernel<<<(NE / 16 + 255) / 256, 256>>>((const int4*)src_idx, (const int4*)dst_idx);

    size_t smem = 16384u * 4 + (size_t)NW * GROUP * 128 * 8 + (size_t)NW * WIN * 4;  // 196608
    cudaFuncSetAttribute(fused_kernel, cudaFuncAttributeMaxDynamicSharedMemorySize, (int)smem);
    fused_kernel<<<NBLK, NTHR, smem>>>(state, b_gate, b_cand, out_ns);

    readout_kernel<<<1, 128>>>(out_ns, eff_idx, W_dec, b_dec, W_mean, b_mean, W_ls, b_ls, out);
}

// round 17
// speedup vs baseline: 1.0700x; 1.0140x over previous
#include <cuda_runtime.h>
#include <cstdint>
#include <cstdio>

#define NB   2
#define NN   50000
#define HH   64
#define NE   1000000
#define NOBS 128
#define NA   18
#define NAFF 512
#define NEFF 256
#define PB   196

#define NBLK   148
#define NW     20
#define NTHR   640
#define WTOT   (NBLK * NW)     // 2960 warps
#define GROUP  5
#define WIN    384             // idx window (ints) per warp

// chunk split: NN = WTOT*16 + 2640 -> first 2640 warps take 17 nodes
#define CHUNK_BIG   17
#define CHUNK_SMALL 16
#define NBIG        (NN - WTOT * CHUNK_SMALL)   // 2640

typedef unsigned int u32;
typedef unsigned long long ull;

// ---------------- device scratch ----------------
__device__ float g_Wp[128 * 128];             // fused weight [k][c]
__device__ float g_projG[NB * HH];
__device__ float g_projC[NB * HH];
__device__ int   g_flag[NN];
__device__ int   g_cnt[NN];
__device__ int   g_off[NN + 1];
__device__ int   g_cur[NN];
__device__ int   g_esrc[NE + WIN];            // padded for cp.async overread
__device__ int   g_part[256];
__device__ unsigned g_sbar;                   // scan grid barrier

// ---------------- helpers ----------------
__device__ __forceinline__ void fma2(ull& d, ull a, ull b) {
    asm("fma.rn.f32x2 %0, %1, %2, %0;" : "+l"(d) : "l"(a), "l"(b));
}
__device__ __forceinline__ void add2(ull& d, ull a) {
    asm("add.rn.f32x2 %0, %0, %1;" : "+l"(d) : "l"(a));
}
__device__ __forceinline__ ull splat2(float w) {
    ull r; unsigned u = __float_as_uint(w);
    asm("mov.b64 %0, {%1, %1};" : "=l"(r) : "r"(u));
    return r;
}
__device__ __forceinline__ ull pack2(float a, float b) {
    ull r;
    asm("mov.b64 %0, {%1, %2};" : "=l"(r) : "r"(__float_as_uint(a)), "r"(__float_as_uint(b)));
    return r;
}
__device__ __forceinline__ float2 u2f2(ull v) {
    float2 f;
    f.x = __uint_as_float((unsigned)v);
    f.y = __uint_as_float((unsigned)(v >> 32));
    return f;
}
__device__ __forceinline__ void cpa16(void* dst, const void* src) {
    unsigned d = (unsigned)__cvta_generic_to_shared(dst);
    asm volatile("cp.async.cg.shared.global [%0], [%1], 16;" :: "r"(d), "l"(src));
}
__device__ __forceinline__ int warp_incl_scan(int v) {
    int lane = threadIdx.x & 31;
#pragma unroll
    for (int d = 1; d < 32; d <<= 1) {
        int t = __shfl_up_sync(0xffffffffu, v, d);
        if (lane >= d) v += t;
    }
    return v;
}
__device__ __forceinline__ float sigm(float x) { return __fdividef(1.f, 1.f + __expf(-x)); }
__device__ __forceinline__ float tanha(float x) { return 1.f - __fdividef(2.f, __expf(2.f * x) + 1.f); }

__device__ __forceinline__ void grid_barrier(unsigned* bar, unsigned expected) {
    __syncthreads();
    if (threadIdx.x == 0) {
        __threadfence();
        atomicAdd(bar, 1u);
        volatile unsigned* vb = bar;
        while (*vb < expected) { }
    }
    __syncthreads();
}

// ---------------- K1: merged prep (proj + flags + fused weight + zeroing) ----------------
__global__ void prep_kernel(const float* __restrict__ obs,
                            const float* __restrict__ W_in,
                            const float* __restrict__ b_in,
                            const float* __restrict__ W_msg,
                            const float* __restrict__ W_gate,
                            const float* __restrict__ W_cand,
                            const int* __restrict__ afferent_idx) {
    if (blockIdx.x == 128) {
        int t = threadIdx.x;
        if (t == 0) { g_sbar = 0u; }
        int4 z4 = make_int4(0, 0, 0, 0);
        for (int i = t; i < NN / 4; i += 128)
            ((int4*)g_flag)[i] = z4;
        __syncthreads();
        __shared__ float proj[NB * HH];
        int b = t >> 6, h = t & 63;
        float acc = b_in[h];
        for (int o = 0; o < NOBS; o++)
            acc += obs[b * NOBS + o] * W_in[o * HH + h];
        proj[b * HH + h] = acc;
        __syncthreads();
        float ag = 0.f, ac = 0.f;
        for (int k = 0; k < HH; k++) {
            float p = proj[b * HH + k];
            ag += p * W_gate[(HH + k) * HH + h];
            ac += p * W_cand[(HH + k) * HH + h];
        }
        g_projG[b * HH + h] = ag;
        g_projC[b * HH + h] = ac;
        for (int i = t; i < NAFF; i += 128)
            g_flag[afferent_idx[i]] = 1;
    } else {
        const int per = (NN + 127) / 128;   // 391
        int s = blockIdx.x * per;
        int e = s + per; if (e > NN) e = NN;
        for (int i = s + threadIdx.x; i < e; i += 128)
            g_cnt[i] = 0;
        int c = blockIdx.x;     // output column 0..127
        int k = threadIdx.x;    // input row 0..127
        float w;
        if (k < HH) {
            w = (c < HH) ? W_gate[k * HH + c] : W_cand[k * HH + (c - HH)];
        } else {
            int km = k - HH;
            float acc = 0.f;
            if (c < HH) {
                for (int t2 = 0; t2 < HH; t2++)
                    acc += W_msg[km * HH + t2] * W_gate[(HH + t2) * HH + c];
            } else {
                for (int t2 = 0; t2 < HH; t2++)
                    acc += W_msg[km * HH + t2] * W_cand[(HH + t2) * HH + (c - HH)];
            }
            w = acc;
        }
        g_Wp[k * 128 + c] = w;
    }
}

// ---------------- K2: histogram ----------------
__global__ void hist_kernel(const int4* __restrict__ dst4) {
    int i = (blockIdx.x * blockDim.x + threadIdx.x) * 2;
    if (i < NE / 4) {
        int4 d0 = __ldg(dst4 + i);
        int4 d1 = __ldg(dst4 + i + 1);
        atomicAdd(&g_cnt[d0.x], 1);
        atomicAdd(&g_cnt[d0.y], 1);
        atomicAdd(&g_cnt[d0.z], 1);
        atomicAdd(&g_cnt[d0.w], 1);
        atomicAdd(&g_cnt[d1.x], 1);
        atomicAdd(&g_cnt[d1.y], 1);
        atomicAdd(&g_cnt[d1.z], 1);
        atomicAdd(&g_cnt[d1.w], 1);
    }
}

// ---------------- K3: single-launch scan ----------------
__global__ void scan_kernel() {            // grid PB, 256 thr
    int b = blockIdx.x;
    int i = b * 256 + threadIdx.x;
    int t = threadIdx.x;
    int lane = t & 31, w = t >> 5;
    __shared__ int ws[8];
    __shared__ int blockBase;

    int v = (i < NN) ? g_cnt[i] : 0;

    int s = v;
#pragma unroll
    for (int d = 16; d > 0; d >>= 1) s += __shfl_down_sync(0xffffffffu, s, d);
    if (lane == 0) ws[w] = s;
    __syncthreads();
    if (t == 0) {
        int tot = 0;
        for (int x = 0; x < 8; x++) tot += ws[x];
        g_part[b] = tot;
    }
    grid_barrier(&g_sbar, PB);

    int pv = (t < PB && t < b) ? g_part[t] : 0;
#pragma unroll
    for (int d = 16; d > 0; d >>= 1) pv += __shfl_down_sync(0xffffffffu, pv, d);
    if (lane == 0) ws[w] = pv;
    __syncthreads();
    if (t == 0) {
        int bs = 0;
        for (int x = 0; x < 8; x++) bs += ws[x];
        blockBase = bs;
    }
    __syncthreads();

    int inc = warp_incl_scan(v);
    if (lane == 31) ws[w] = inc;
    __syncthreads();
    if (w == 0) {
        int qv = (lane < 8) ? ws[lane] : 0;
        int qi = warp_incl_scan(qv);
        if (lane < 8) ws[lane] = qi;
    }
    __syncthreads();
    int base = (w > 0) ? ws[w - 1] : 0;
    int off = blockBase + base + inc - v;
    if (i < NN) { g_off[i] = off; g_cur[i] = off; }
    if (i == 0) g_off[NN] = NE;
}

// ---------------- K4: scatter ----------------
__global__ void scatter_kernel(const int4* __restrict__ src4,
                               const int4* __restrict__ dst4) {
    int i = (blockIdx.x * blockDim.x + threadIdx.x) * 2;
    if (i < NE / 4) {
        int4 s0 = __ldg(src4 + i);
        int4 d0 = __ldg(dst4 + i);
        int4 s1 = __ldg(src4 + i + 1);
        int4 d1 = __ldg(dst4 + i + 1);
        g_esrc[atomicAdd(&g_cur[d0.x], 1)] = s0.x;
        g_esrc[atomicAdd(&g_cur[d0.y], 1)] = s0.y;
        g_esrc[atomicAdd(&g_cur[d0.z], 1)] = s0.z;
        g_esrc[atomicAdd(&g_cur[d0.w], 1)] = s0.w;
        g_esrc[atomicAdd(&g_cur[d1.x], 1)] = s1.x;
        g_esrc[atomicAdd(&g_cur[d1.y], 1)] = s1.y;
        g_esrc[atomicAdd(&g_cur[d1.z], 1)] = s1.z;
        g_esrc[atomicAdd(&g_cur[d1.w], 1)] = s1.w;
    }
}

// ---------------- K5: fused gather + f32x2 GEMM + GRU epilogue ----------------
// 20 warps/block (5/SMSP), GROUP=5, 96 regs/thread: clean occupancy experiment
// over the proven R12 structure (8-deep gather unroll, single add2 chains).
__global__ void __launch_bounds__(NTHR, 1) fused_kernel(const float* __restrict__ state,
                                                        const float* __restrict__ b_gate,
                                                        const float* __restrict__ b_cand,
                                                        float* __restrict__ out_ns) {
    extern __shared__ float smem[];
    float* Ws = smem;                                    // 16384 floats
    ull* xs = (ull*)(smem + 16384);                      // NW * GROUP * 128 ull
    int* sIdx = (int*)(xs + NW * GROUP * 128);           // NW * WIN ints

    int tid = threadIdx.x;
    for (int i = tid; i < 4096; i += NTHR)
        ((float4*)Ws)[i] = ((const float4*)g_Wp)[i];
    __syncthreads();

    int warp = tid >> 5, lane = tid & 31;
    int q = lane & 15;
    int cc0 = q * 4;
    bool zside = lane < 16;
    int l4 = lane & 15;
    int half = lane >> 4;      // 0: batch0, 1: batch1

    float bias[4], pj0[4], pj1[4];
#pragma unroll
    for (int c = 0; c < 4; c++) {
        int cc = cc0 + c;
        if (zside) { bias[c] = __ldg(b_gate + cc); pj0[c] = g_projG[cc]; pj1[c] = g_projG[64 + cc]; }
        else       { bias[c] = __ldg(b_cand + cc); pj0[c] = g_projC[cc]; pj1[c] = g_projC[64 + cc]; }
    }

    ull* mx = xs + warp * (GROUP * 128);
    int* widx = sIdx + warp * WIN;
    int gwid = blockIdx.x * NW + warp;
    const ulonglong2* U2 = (const ulonglong2*)state + (size_t)half * NN * 16;

    int cBase, cCnt;
    if (gwid < NBIG) { cBase = gwid * CHUNK_BIG; cCnt = CHUNK_BIG; }
    else             { cBase = NBIG * CHUNK_BIG + (gwid - NBIG) * CHUNK_SMALL; cCnt = CHUNK_SMALL; }
    int nEnd = cBase + cCnt;

    // stage index window for the chunk
    int slab = __ldg(&g_off[cBase]) & ~3;
    for (int c = lane; c < WIN / 4; c += 32)
        cpa16(widx + c * 4, g_esrc + slab + c * 4);
    asm volatile("cp.async.commit_group;" ::: "memory");
    asm volatile("cp.async.wait_group 0;" ::: "memory");
    __syncwarp();

    int sg = 1 + (gwid % GROUP);       // staggered first sub-group size
    int n0 = cBase;
    while (n0 < nEnd) {
        int cnt = nEnd - n0;
        if (cnt > sg) cnt = sg;
        sg = GROUP;
        int flg[GROUP];

        // ---- gather phase (split-batch LDG.128 + f32x2 accumulate, 8-unroll) ----
        for (int m = 0; m < cnt; m++) {
            int n = n0 + m;
            int beg = __ldg(&g_off[n]), end = __ldg(&g_off[n + 1]);
            flg[m] = __ldg(&g_flag[n]);
            ull a0 = 0ull, a1 = 0ull;
            int j = beg;
            while (j < end) {
                if (j >= slab + WIN) {           // refill window (rare)
                    slab = j & ~3;
                    for (int c = lane; c < WIN / 4; c += 32)
                        cpa16(widx + c * 4, g_esrc + slab + c * 4);
                    asm volatile("cp.async.commit_group;" ::: "memory");
                    asm volatile("cp.async.wait_group 0;" ::: "memory");
                    __syncwarp();
                }
                int lim = slab + WIN;
                if (lim > end) lim = end;
                for (; j + 8 <= lim; j += 8) {
                    int e[8];
#pragma unroll
                    for (int u = 0; u < 8; u++) e[u] = widx[j - slab + u];
                    ulonglong2 v[8];
#pragma unroll
                    for (int u = 0; u < 8; u++)
                        v[u] = __ldg(U2 + (size_t)e[u] * 16 + l4);
#pragma unroll
                    for (int u = 0; u < 8; u++) {
                        add2(a0, v[u].x);
                        add2(a1, v[u].y);
                    }
                }
                for (; j < lim; j++) {
                    int e0 = widx[j - slab];
                    ulonglong2 v0 = __ldg(U2 + (size_t)e0 * 16 + l4);
                    add2(a0, v0.x);
                    add2(a1, v0.y);
                }
            }
            ulonglong2 so = __ldg(U2 + (size_t)n * 16 + l4);
            ull po0 = __shfl_xor_sync(0xffffffffu, so.x, 16);
            ull po1 = __shfl_xor_sync(0xffffffffu, so.y, 16);
            ull qa0 = __shfl_xor_sync(0xffffffffu, a0, 16);
            ull qa1 = __shfl_xor_sync(0xffffffffu, a1, 16);
            ull* row = mx + m * 128;
            if (lane < 16) {
                float2 o0 = u2f2(so.x), o1 = u2f2(so.y);   // b0 state
                float2 p0 = u2f2(po0),  p1 = u2f2(po1);    // b1 state
                ((float4*)row)[2 * l4]     = make_float4(o0.x, p0.x, o0.y, p0.y);
                ((float4*)row)[2 * l4 + 1] = make_float4(o1.x, p1.x, o1.y, p1.y);
            } else {
                float2 o0 = u2f2(a0),  o1 = u2f2(a1);      // b1 agg
                float2 p0 = u2f2(qa0), p1 = u2f2(qa1);     // b0 agg
                ((float4*)(row + 64))[2 * l4]     = make_float4(p0.x, o0.x, p0.y, o0.y);
                ((float4*)(row + 64))[2 * l4 + 1] = make_float4(p1.x, o1.x, p1.y, o1.y);
            }
        }
        __syncwarp();

        // ---- FMA phase (batch-paired, splat weights) ----
        ull acc6[GROUP][4];
#pragma unroll
        for (int m = 0; m < GROUP; m++)
#pragma unroll
            for (int c = 0; c < 4; c++) acc6[m][c] = 0ull;

#pragma unroll 4
        for (int k = 0; k < 128; k += 2) {
            float4 wA = ((const float4*)(Ws + k * 128))[lane];
            float4 wB = ((const float4*)(Ws + (k + 1) * 128))[lane];
            ull wa0 = splat2(wA.x), wa1 = splat2(wA.y), wa2 = splat2(wA.z), wa3 = splat2(wA.w);
            ull wb0 = splat2(wB.x), wb1 = splat2(wB.y), wb2 = splat2(wB.z), wb3 = splat2(wB.w);
#pragma unroll
            for (int m = 0; m < GROUP; m++) {
                ulonglong2 xv = ((const ulonglong2*)(mx + m * 128))[k >> 1];
                fma2(acc6[m][0], wa0, xv.x); fma2(acc6[m][1], wa1, xv.x);
                fma2(acc6[m][2], wa2, xv.x); fma2(acc6[m][3], wa3, xv.x);
                fma2(acc6[m][0], wb0, xv.y); fma2(acc6[m][1], wb1, xv.y);
                fma2(acc6[m][2], wb2, xv.y); fma2(acc6[m][3], wb3, xv.y);
            }
        }

        // ---- epilogue ----
        for (int m = 0; m < cnt; m++) {
            int n = n0 + m;
            ull actp[4];
#pragma unroll
            for (int c = 0; c < 4; c++) {
                float2 pre = u2f2(acc6[m][c]);
                float p0 = pre.x + bias[c] + (flg[m] ? pj0[c] : 0.f);
                float p1 = pre.y + bias[c] + (flg[m] ? pj1[c] : 0.f);
                float a0f, a1f;
                if (zside) { a0f = sigm(p0);  a1f = sigm(p1); }
                else       { a0f = tanha(p0); a1f = tanha(p1); }
                actp[c] = pack2(a0f, a1f);
            }
            ull oth[4];
#pragma unroll
            for (int c = 0; c < 4; c++)
                oth[c] = __shfl_xor_sync(0xffffffffu, actp[c], 16);
            if (zside) {
                float4 r0, r1;
                float* q0 = (float*)&r0;
                float* q1 = (float*)&r1;
#pragma unroll
                for (int c = 0; c < 4; c++) {
                    float2 z = u2f2(actp[c]);
                    float2 t = u2f2(oth[c]);
                    float2 sp = u2f2(mx[m * 128 + cc0 + c]);
                    q0[c] = fmaf(z.x, t.x - sp.x, sp.x);
                    q1[c] = fmaf(z.y, t.y - sp.y, sp.y);
                }
                *((float4*)(out_ns + (size_t)n * 64 + cc0)) = r0;
                *((float4*)(out_ns + ((size_t)NN + n) * 64 + cc0)) = r1;
            }
        }
        __syncwarp();
        n0 += cnt;
    }
}

// ---------------- K6: readout + policy heads ----------------
__global__ void readout_kernel(const float* __restrict__ ns,
                               const int* __restrict__ efferent_idx,
                               const float* __restrict__ W_dec,
                               const float* __restrict__ b_dec,
                               const float* __restrict__ W_mean,
                               const float* __restrict__ b_mean,
                               const float* __restrict__ W_ls,
                               const float* __restrict__ b_ls,
                               float* __restrict__ out) {
    __shared__ float ro[NB * HH];
    __shared__ float dec[NB * HH];
    int t = threadIdx.x;
    int b = t >> 6, h = t & 63;
    float sum = 0.f;
    for (int i = 0; i < NEFF; i++) {
        int idx = efferent_idx[i];
        sum += ns[((size_t)b * NN + idx) * HH + h];
    }
    ro[b * HH + h] = sum * (1.f / NEFF);
    __syncthreads();
    float acc = b_dec[h];
    for (int k = 0; k < HH; k++)
        acc += ro[b * HH + k] * W_dec[k * HH + h];
    dec[b * HH + h] = tanhf(acc);
    __syncthreads();
    if (t < NB * NA) {
        int bb = t / NA, a = t % NA;
        float m = b_mean[a], ls = b_ls[a];
        for (int k = 0; k < HH; k++) {
            float d = dec[bb * HH + k];
            m  += d * W_mean[k * NA + a];
            ls += d * W_ls[k * NA + a];
        }
        ls = fminf(fmaxf(ls, -5.f), 2.f);
        out[bb * NA + a] = m;
        out[NB * NA + bb * NA + a] = ls;
    }
}

// ---------------- launch ----------------
extern "C" void kernel_launch(void* const* d_in, const int* in_sizes, int n_in,
                              void* d_out, int out_size) {
    const float* obs    = (const float*)d_in[0];
    const float* state  = (const float*)d_in[1];
    const float* W_in   = (const float*)d_in[2];
    const float* b_in   = (const float*)d_in[3];
    const float* W_msg  = (const float*)d_in[4];
    const float* W_gate = (const float*)d_in[5];
    const float* b_gate = (const float*)d_in[6];
    const float* W_cand = (const float*)d_in[7];
    const float* b_cand = (const float*)d_in[8];
    const float* W_dec  = (const float*)d_in[9];
    const float* b_dec  = (const float*)d_in[10];
    const float* W_mean = (const float*)d_in[11];
    const float* b_mean = (const float*)d_in[12];
    const float* W_ls   = (const float*)d_in[13];
    const float* b_ls   = (const float*)d_in[14];
    const int* src_idx  = (const int*)d_in[15];
    const int* dst_idx  = (const int*)d_in[16];
    const int* aff_idx  = (const int*)d_in[17];
    const int* eff_idx  = (const int*)d_in[18];
    float* out = (float*)d_out;
    float* out_ns = out + 2 * NB * NA;

    prep_kernel<<<129, 128>>>(obs, W_in, b_in, W_msg, W_gate, W_cand, aff_idx);
    hist_kernel<<<(NE / 8 + 255) / 256, 256>>>((const int4*)dst_idx);
    scan_kernel<<<PB, 256>>>();
    scatter_kernel<<<(NE / 8 + 255) / 256, 256>>>((const int4*)src_idx, (const int4*)dst_idx);

    size_t smem = 16384u * 4 + (size_t)NW * GROUP * 128 * 8 + (size_t)NW * WIN * 4;  // 198656
    cudaFuncSetAttribute(fused_kernel, cudaFuncAttributeMaxDynamicSharedMemorySize, (int)smem);
    fused_kernel<<<NBLK, NTHR, smem>>>(state, b_gate, b_cand, out_ns);

    readout_kernel<<<1, 128>>>(out_ns, eff_idx, W_dec, b_dec, W_mean, b_mean, W_ls, b_ls, out);
}